// round 16
// baseline (speedup 1.0000x reference)
#include <cuda_runtime.h>
#include <math.h>

// Spherization, per row r (512 features):
//   ang_j = A*sigmoid(scaling*x) + phiL
//   out[k]   = radius * prod_{j<k}(sin(ang_j)+eps) * sgn(cos_k)*(|cos(ang_k)|+eps)
//   out[512] = radius * prod_j (sin(ang_j)+eps)
// R6 compute pipeline (MUFU.TANH sigmoid, MUFU.SIN/COS) + R12/R15 store path
// (phase-shifted STG.128, .cs streaming, no SMEM).
// R16: TWO rows per warp, both rows' inputs prefetched up front (MLP=8 per
// warp) before sequential per-row processing — row B's load latency is hidden
// under row A's compute. Row pair is (even, odd): phases (0,1) or (2,3).

#define NFEAT 512
#define ROW_OUT 513
#define WARPS_PER_BLOCK 8
#define EPSf 1e-6f

static __device__ __forceinline__ void stcs4(float* p, float a, float b, float c, float d) {
    asm volatile("st.global.cs.v4.f32 [%0], {%1,%2,%3,%4};"
                 :: "l"(p), "f"(a), "f"(b), "f"(c), "f"(d) : "memory");
}
static __device__ __forceinline__ void stcs2(float* p, float a, float b) {
    asm volatile("st.global.cs.v2.f32 [%0], {%1,%2};"
                 :: "l"(p), "f"(a), "f"(b) : "memory");
}
static __device__ __forceinline__ void stcs1(float* p, float a) {
    asm volatile("st.global.cs.f32 [%0], %1;" :: "l"(p), "f"(a) : "memory");
}

// Process one row whose input is already in registers (v[4]).
template<int P>
__device__ __forceinline__ void row_proc(const float4* v,
                                         float* __restrict__ orow,
                                         float hmul, float halfA, float mid,
                                         float radius, int lane)
{
    float carry = radius;
    float tail0 = 0.0f, tail1 = 0.0f;            // P=1,2: prev block lane31 tail
    float pend1 = 0.0f, pend2 = 0.0f, pend3 = 0.0f;  // P=3: lane31 deferred

    #pragma unroll
    for (int j = 0; j < 4; j++) {
        float vv[4] = {v[j].x, v[j].y, v[j].z, v[j].w};
        float sv[4], cv[4];
        #pragma unroll
        for (int m = 0; m < 4; m++) {
            float t = vv[m] * hmul;
            float u;  asm("tanh.approx.f32 %0, %1;" : "=f"(u) : "f"(t));
            float ang = fmaf(halfA, u, mid);          // in [phiL, pi - phiL]
            float sn  = __sinf(ang);                  // > 0 on range
            float cs  = __cosf(ang);
            sv[m] = sn + EPSf;
            cv[m] = copysignf(fabsf(cs) + EPSf, cs);
        }
        // local exclusive prefixes
        float e1  = sv[0];
        float e2  = e1 * sv[1];
        float e3  = e2 * sv[2];
        float tot = e3 * sv[3];

        // warp-inclusive scan of per-lane block totals
        float incl = tot;
        #pragma unroll
        for (int d = 1; d < 32; d <<= 1) {
            float t2 = __shfl_up_sync(0xFFFFFFFFu, incl, d);
            if (lane >= d) incl *= t2;
        }
        float excl = __shfl_up_sync(0xFFFFFFFFu, incl, 1);
        if (lane == 0) excl = 1.0f;
        float bp = carry * excl;

        float o0 = bp * cv[0];
        float o1 = (bp * e1) * cv[1];
        float o2 = (bp * e2) * cv[2];
        float o3 = (bp * e3) * cv[3];

        if constexpr (P == 0) {
            stcs4(orow + 128 * j + 4 * lane, o0, o1, o2, o3);
        } else if constexpr (P == 1) {
            float t0 = __shfl_up_sync(0xFFFFFFFFu, o3, 1);
            if (lane == 0) t0 = tail0;               // prev block lane31 o3
            if (j > 0 || lane > 0)
                stcs4(orow + 128 * j + 4 * lane - 1, t0, o0, o1, o2);
            tail0 = __shfl_sync(0xFFFFFFFFu, o3, 31);
            if (j == 0 && lane == 0) {
                stcs1(orow, o0); stcs2(orow + 1, o1, o2);
            }
        } else if constexpr (P == 2) {
            float t0 = __shfl_up_sync(0xFFFFFFFFu, o2, 1);
            float t1 = __shfl_up_sync(0xFFFFFFFFu, o3, 1);
            if (lane == 0) { t0 = tail0; t1 = tail1; }
            if (j > 0 || lane > 0)
                stcs4(orow + 128 * j + 4 * lane - 2, t0, t1, o0, o1);
            tail0 = __shfl_sync(0xFFFFFFFFu, o2, 31);
            tail1 = __shfl_sync(0xFFFFFFFFu, o3, 31);
            if (j == 0 && lane == 0) stcs2(orow, o0, o1);
        } else {  // P == 3: shift +1 (cheaper than borrowing 3)
            float b = __shfl_sync(0xFFFFFFFFu, o0, 0);   // this block's element 128j
            if (j > 0 && lane == 31)                     // deferred prev-block vector
                stcs4(orow + 128 * (j - 1) + 125, pend1, pend2, pend3, b);
            float t3 = __shfl_down_sync(0xFFFFFFFFu, o0, 1);  // next lane's o0
            if (lane < 31)
                stcs4(orow + 128 * j + 4 * lane + 1, o1, o2, o3, t3);
            else { pend1 = o1; pend2 = o2; pend3 = o3; }
            if (j == 0 && lane == 0) stcs1(orow, o0);
        }

        carry *= __shfl_sync(0xFFFFFFFFu, incl, 31);
    }

    // row tails (addresses aligned for their width)
    if constexpr (P == 0) {
        if (lane == 0) stcs1(orow + NFEAT, carry);
    } else if constexpr (P == 1) {
        if (lane == 0)   // tail0 = element 511, carry = element 512
            stcs2(orow + 511, tail0, carry);
    } else if constexpr (P == 2) {
        if (lane == 0) { // tail0,tail1 = elements 510,511
            stcs2(orow + 510, tail0, tail1);
            stcs1(orow + NFEAT, carry);
        }
    } else {
        if (lane == 31)  // elements 509,510,511,512
            stcs4(orow + 509, pend1, pend2, pend3, carry);
    }
}

__global__ __launch_bounds__(WARPS_PER_BLOCK * 32)
void spherization_kernel(const float* __restrict__ x,
                         const float* __restrict__ scaling_p,
                         const float* __restrict__ radius_p,
                         float* __restrict__ out,
                         int nrows, float halfA, float mid)
{
    const int wib  = threadIdx.x >> 5;
    const int lane = threadIdx.x & 31;
    const int pair = blockIdx.x * WARPS_PER_BLOCK + wib;   // row pair index
    const int row0 = 2 * pair;
    if (row0 >= nrows) return;
    const bool haveB = (row0 + 1) < nrows;

    const float scaling = __ldg(scaling_p);
    const float radius  = __ldg(radius_p);
    const float hmul = 0.5f * scaling;     // t = hmul*x ; u = tanh(t)

    const float4* xrA = reinterpret_cast<const float4*>(x + (size_t)row0 * NFEAT);
    const float4* xrB = xrA + NFEAT / 4;
    float* orowA = out + (size_t)row0 * ROW_OUT;
    float* orowB = orowA + ROW_OUT;

    // prefetch BOTH rows up front: MLP=8 per warp
    float4 vA[4], vB[4];
    #pragma unroll
    for (int j = 0; j < 4; j++) vA[j] = xrA[lane + 32 * j];
    if (haveB) {
        #pragma unroll
        for (int j = 0; j < 4; j++) vB[j] = xrB[lane + 32 * j];
    }

    if ((row0 & 3) == 0) {   // rows (4t, 4t+1): phases 0 and 1
        row_proc<0>(vA, orowA, hmul, halfA, mid, radius, lane);
        if (haveB) row_proc<1>(vB, orowB, hmul, halfA, mid, radius, lane);
    } else {                 // rows (4t+2, 4t+3): phases 2 and 3
        row_proc<2>(vA, orowA, hmul, halfA, mid, radius, lane);
        if (haveB) row_proc<3>(vB, orowB, hmul, halfA, mid, radius, lane);
    }
}

extern "C" void kernel_launch(void* const* d_in, const int* in_sizes, int n_in,
                              void* d_out, int out_size)
{
    int xi = 0;
    for (int i = 0; i < n_in; i++) if (in_sizes[i] > in_sizes[xi]) xi = i;
    int others[2]; int no = 0;
    for (int i = 0; i < n_in && no < 2; i++) if (i != xi) others[no++] = i;

    const float* x   = (const float*)d_in[xi];
    const float* sc  = (const float*)d_in[others[0]];   // scaling
    const float* rad = (const float*)d_in[others[1]];   // radius

    float* out = (float*)d_out;
    int nrows = in_sizes[xi] / NFEAT;

    // constants in double; PI truncated exactly as in the reference
    const double PI_d = 3.141592;
    double phiL = asin(pow(1e-6, 1.0 / 512.0));
    double phiU = PI_d / 2.0 * (1.0 - 0.01);
    if (phiU < phiL) phiL = phiU;
    double A = PI_d - 2.0 * phiL;
    float halfA = (float)(0.5 * A);          // ang = halfA*u + (halfA + phiL)
    float mid   = (float)(0.5 * A + phiL);

    int npairs = (nrows + 1) / 2;
    int blocks = (npairs + WARPS_PER_BLOCK - 1) / WARPS_PER_BLOCK;
    spherization_kernel<<<blocks, WARPS_PER_BLOCK * 32>>>(
        x, sc, rad, out, nrows, halfA, mid);
}

// round 17
// speedup vs baseline: 1.0383x; 1.0383x over previous
#include <cuda_runtime.h>
#include <math.h>

// Spherization, per row r (512 features):
//   ang_j = A*sigmoid(scaling*x) + phiL
//   out[k]   = radius * prod_{j<k}(sin(ang_j)+eps) * sgn(cos_k)*(|cos(ang_k)|+eps)
//   out[512] = radius * prod_j (sin(ang_j)+eps)
//
// FINAL (R15, measured optimum over 16 rounds; kernel 38.56us, DRAM-ceiling
// bound at ~5.5 TB/s mixed R/W):
//  - MUFU.TANH sigmoid: sigmoid(z) = (1+tanh(z/2))/2 -> ang = fma(halfA,u,mid)
//    (element pipeline: FMUL, TANH, FFMA, SIN, COS, FADD, |.|+eps — 3 MUFU,
//     the issue-minimal form; every cheaper-XU variant measured slower)
//  - full MLP=4 input prefetch (load-bearing)
//  - per-block local prefixes + chained warp scans (shfl)
//  - NO SMEM: direct phase-shifted STG.128. Row base alignment = 4*(row%4)
//    bytes; lane's float4 lands at element k = 128j+4*lane-P (P=row&3),
//    16B-aligned for every row; vectors assembled via shfl borrow (P=1,2) or
//    +1 shift with deferred lane-31 vector (P=3). Every store instruction is
//    warp-contiguous (full sectors; L2 does NOT merge partial sectors).
//  - streaming (.cs, evict-first) stores: output is write-once.

#define NFEAT 512
#define ROW_OUT 513
#define WARPS_PER_BLOCK 8
#define EPSf 1e-6f

static __device__ __forceinline__ void stcs4(float* p, float a, float b, float c, float d) {
    asm volatile("st.global.cs.v4.f32 [%0], {%1,%2,%3,%4};"
                 :: "l"(p), "f"(a), "f"(b), "f"(c), "f"(d) : "memory");
}
static __device__ __forceinline__ void stcs2(float* p, float a, float b) {
    asm volatile("st.global.cs.v2.f32 [%0], {%1,%2};"
                 :: "l"(p), "f"(a), "f"(b) : "memory");
}
static __device__ __forceinline__ void stcs1(float* p, float a) {
    asm volatile("st.global.cs.f32 [%0], %1;" :: "l"(p), "f"(a) : "memory");
}

template<int P>
__device__ __forceinline__ void row_proc(const float4* __restrict__ xr,
                                         float* __restrict__ orow,
                                         float hmul, float halfA, float mid,
                                         float radius, int lane)
{
    // prefetch all loads (MLP=4), coalesced LDG.128 — load-bearing
    float4 v[4];
    #pragma unroll
    for (int j = 0; j < 4; j++) v[j] = xr[lane + 32 * j];

    float carry = radius;
    float tail0 = 0.0f, tail1 = 0.0f;            // P=1,2: prev block lane31 tail
    float pend1 = 0.0f, pend2 = 0.0f, pend3 = 0.0f;  // P=3: lane31 deferred

    #pragma unroll
    for (int j = 0; j < 4; j++) {
        float vv[4] = {v[j].x, v[j].y, v[j].z, v[j].w};
        float sv[4], cv[4];
        #pragma unroll
        for (int m = 0; m < 4; m++) {
            float t = vv[m] * hmul;
            float u;  asm("tanh.approx.f32 %0, %1;" : "=f"(u) : "f"(t));
            float ang = fmaf(halfA, u, mid);          // in [phiL, pi - phiL]
            float sn  = __sinf(ang);                  // > 0 on range
            float cs  = __cosf(ang);
            sv[m] = sn + EPSf;
            cv[m] = copysignf(fabsf(cs) + EPSf, cs);
        }
        // local exclusive prefixes
        float e1  = sv[0];
        float e2  = e1 * sv[1];
        float e3  = e2 * sv[2];
        float tot = e3 * sv[3];

        // warp-inclusive scan of per-lane block totals
        float incl = tot;
        #pragma unroll
        for (int d = 1; d < 32; d <<= 1) {
            float t2 = __shfl_up_sync(0xFFFFFFFFu, incl, d);
            if (lane >= d) incl *= t2;
        }
        float excl = __shfl_up_sync(0xFFFFFFFFu, incl, 1);
        if (lane == 0) excl = 1.0f;
        float bp = carry * excl;

        float o0 = bp * cv[0];
        float o1 = (bp * e1) * cv[1];
        float o2 = (bp * e2) * cv[2];
        float o3 = (bp * e3) * cv[3];

        if constexpr (P == 0) {
            stcs4(orow + 128 * j + 4 * lane, o0, o1, o2, o3);
        } else if constexpr (P == 1) {
            float t0 = __shfl_up_sync(0xFFFFFFFFu, o3, 1);
            if (lane == 0) t0 = tail0;               // prev block lane31 o3
            if (j > 0 || lane > 0)
                stcs4(orow + 128 * j + 4 * lane - 1, t0, o0, o1, o2);
            tail0 = __shfl_sync(0xFFFFFFFFu, o3, 31);
            if (j == 0 && lane == 0) {
                stcs1(orow, o0); stcs2(orow + 1, o1, o2);
            }
        } else if constexpr (P == 2) {
            float t0 = __shfl_up_sync(0xFFFFFFFFu, o2, 1);
            float t1 = __shfl_up_sync(0xFFFFFFFFu, o3, 1);
            if (lane == 0) { t0 = tail0; t1 = tail1; }
            if (j > 0 || lane > 0)
                stcs4(orow + 128 * j + 4 * lane - 2, t0, t1, o0, o1);
            tail0 = __shfl_sync(0xFFFFFFFFu, o2, 31);
            tail1 = __shfl_sync(0xFFFFFFFFu, o3, 31);
            if (j == 0 && lane == 0) stcs2(orow, o0, o1);
        } else {  // P == 3: shift +1 (cheaper than borrowing 3)
            float b = __shfl_sync(0xFFFFFFFFu, o0, 0);   // this block's element 128j
            if (j > 0 && lane == 31)                     // deferred prev-block vector
                stcs4(orow + 128 * (j - 1) + 125, pend1, pend2, pend3, b);
            float t3 = __shfl_down_sync(0xFFFFFFFFu, o0, 1);  // next lane's o0
            if (lane < 31)
                stcs4(orow + 128 * j + 4 * lane + 1, o1, o2, o3, t3);
            else { pend1 = o1; pend2 = o2; pend3 = o3; }
            if (j == 0 && lane == 0) stcs1(orow, o0);
        }

        carry *= __shfl_sync(0xFFFFFFFFu, incl, 31);
    }

    // row tails (addresses aligned for their width)
    if constexpr (P == 0) {
        if (lane == 0) stcs1(orow + NFEAT, carry);
    } else if constexpr (P == 1) {
        if (lane == 0)   // tail0 = element 511, carry = element 512
            stcs2(orow + 511, tail0, carry);
    } else if constexpr (P == 2) {
        if (lane == 0) { // tail0,tail1 = elements 510,511
            stcs2(orow + 510, tail0, tail1);
            stcs1(orow + NFEAT, carry);
        }
    } else {
        if (lane == 31)  // elements 509,510,511,512
            stcs4(orow + 509, pend1, pend2, pend3, carry);
    }
}

__global__ __launch_bounds__(WARPS_PER_BLOCK * 32)
void spherization_kernel(const float* __restrict__ x,
                         const float* __restrict__ scaling_p,
                         const float* __restrict__ radius_p,
                         float* __restrict__ out,
                         int nrows, float halfA, float mid)
{
    const int wib  = threadIdx.x >> 5;
    const int lane = threadIdx.x & 31;
    const int row  = blockIdx.x * WARPS_PER_BLOCK + wib;
    if (row >= nrows) return;

    const float scaling = __ldg(scaling_p);
    const float radius  = __ldg(radius_p);
    const float hmul = 0.5f * scaling;     // t = hmul*x ; u = tanh(t)

    const float4* xr = reinterpret_cast<const float4*>(x + (size_t)row * NFEAT);
    float* orow = out + (size_t)row * ROW_OUT;

    switch (row & 3) {   // == wib & 3 : warp-uniform
        case 0: row_proc<0>(xr, orow, hmul, halfA, mid, radius, lane); break;
        case 1: row_proc<1>(xr, orow, hmul, halfA, mid, radius, lane); break;
        case 2: row_proc<2>(xr, orow, hmul, halfA, mid, radius, lane); break;
        default: row_proc<3>(xr, orow, hmul, halfA, mid, radius, lane); break;
    }
}

extern "C" void kernel_launch(void* const* d_in, const int* in_sizes, int n_in,
                              void* d_out, int out_size)
{
    int xi = 0;
    for (int i = 0; i < n_in; i++) if (in_sizes[i] > in_sizes[xi]) xi = i;
    int others[2]; int no = 0;
    for (int i = 0; i < n_in && no < 2; i++) if (i != xi) others[no++] = i;

    const float* x   = (const float*)d_in[xi];
    const float* sc  = (const float*)d_in[others[0]];   // scaling
    const float* rad = (const float*)d_in[others[1]];   // radius

    float* out = (float*)d_out;
    int nrows = in_sizes[xi] / NFEAT;

    // constants in double; PI truncated exactly as in the reference
    const double PI_d = 3.141592;
    double phiL = asin(pow(1e-6, 1.0 / 512.0));
    double phiU = PI_d / 2.0 * (1.0 - 0.01);
    if (phiU < phiL) phiL = phiU;
    double A = PI_d - 2.0 * phiL;
    float halfA = (float)(0.5 * A);          // ang = halfA*u + (halfA + phiL)
    float mid   = (float)(0.5 * A + phiL);

    int blocks = (nrows + WARPS_PER_BLOCK - 1) / WARPS_PER_BLOCK;
    spherization_kernel<<<blocks, WARPS_PER_BLOCK * 32>>>(
        x, sc, rad, out, nrows, halfA, mid);
}